// round 3
// baseline (speedup 1.0000x reference)
#include <cuda_runtime.h>
#include <cuda_bf16.h>
#include <math.h>

#define TT 2048
#define DD 1024
#define HH 1024
#define NBLK 16
#define LYR 4
#define RANKK 64
#define NMEM 64
#define VV 50304
#define RMS_EPS 1.1920929e-7f
#define SEGLEN 32
#define NSEG 64

// ---------------- scratch (static device arrays; no allocation) ----------------
__device__ float g_x[TT * DD];
__device__ float g_e[TT * DD];
__device__ float g_h[TT * DD];     // drive_seq -> h_seq (scan in place)
__device__ float g_ud[TT * DD];    // depth drive
__device__ float g_c[TT * 3 * DD]; // concat [hn, e, shifted]
__device__ float g_r[TT * DD];
__device__ float g_tmp[TT * RANKK];
__device__ float g_xn[TT * DD];
__device__ float g_seg[NSEG * DD];

// ---------------- helpers ----------------
__device__ __forceinline__ float silu_f(float x) { return x / (1.0f + expf(-x)); }

__device__ __forceinline__ float tf32r(float x) {
    unsigned u;
    asm("cvt.rna.tf32.f32 %0, %1;" : "=r"(u) : "f"(x));
    return __uint_as_float(u);
}

// ---------------- embedding ----------------
__global__ void embed_kernel(const int* __restrict__ idx, const float* __restrict__ wte,
                             const float* __restrict__ wpe, float* __restrict__ x) {
    int t = blockIdx.x;
    int row = idx[t];
    const float4* wrow = (const float4*)(wte + (long)row * DD);
    const float4* prow = (const float4*)(wpe + (long)t * DD);
    float4* xo = (float4*)(x + t * DD);
    for (int d = threadIdx.x; d < DD / 4; d += blockDim.x) {
        float4 a = wrow[d], b = prow[d];
        xo[d] = make_float4(a.x + b.x, a.y + b.y, a.z + b.z, a.w + b.w);
    }
}

// ---------------- rmsnorm ----------------
__global__ void rmsnorm_kernel(const float* __restrict__ in, float* __restrict__ out) {
    int t = blockIdx.x;
    int tid = threadIdx.x;
    float4 v = ((const float4*)(in + t * DD))[tid];
    float ss = v.x * v.x + v.y * v.y + v.z * v.z + v.w * v.w;
    __shared__ float red[256];
    red[tid] = ss;
    __syncthreads();
    for (int s = 128; s > 0; s >>= 1) {
        if (tid < s) red[tid] += red[tid + s];
        __syncthreads();
    }
    float sc = rsqrtf(red[0] / (float)DD + RMS_EPS);
    ((float4*)(out + t * DD))[tid] = make_float4(v.x * sc, v.y * sc, v.z * sc, v.w * sc);
}

// ============ dual block-diagonal GEMM, K=64, silu: h=silu(e@W1^T), ud=silu(e@W2^T) =======
// grid (TT/64, NBLK), block 256. Output tile [64 t][64 o] for block n, for BOTH weights.
__global__ void __launch_bounds__(256)
bd64_dual_kernel(const float* __restrict__ in, const float* __restrict__ W1,
                 const float* __restrict__ W2, float* __restrict__ out1,
                 float* __restrict__ out2) {
    __shared__ float As[64 * 64];   // [t][k]
    __shared__ float Ws1[64 * 64];  // [k][o]
    __shared__ float Ws2[64 * 64];
    const int t0 = blockIdx.x * 64;
    const int n = blockIdx.y;
    const int tid = threadIdx.x;
    const int tx = tid & 15, ty = tid >> 4;

    for (int i = tid; i < 1024; i += 256) {
        int t = i >> 4, kc = (i & 15) << 2;
        *(float4*)&As[t * 64 + kc] = *(const float4*)&in[(t0 + t) * DD + n * 64 + kc];
    }
    for (int i = tid; i < 1024; i += 256) {
        int o = i >> 4, kc = (i & 15) << 2;
        float4 w = *(const float4*)&W1[(n * 64 + o) * 64 + kc];
        Ws1[(kc + 0) * 64 + o] = w.x; Ws1[(kc + 1) * 64 + o] = w.y;
        Ws1[(kc + 2) * 64 + o] = w.z; Ws1[(kc + 3) * 64 + o] = w.w;
        float4 u = *(const float4*)&W2[(n * 64 + o) * 64 + kc];
        Ws2[(kc + 0) * 64 + o] = u.x; Ws2[(kc + 1) * 64 + o] = u.y;
        Ws2[(kc + 2) * 64 + o] = u.z; Ws2[(kc + 3) * 64 + o] = u.w;
    }
    __syncthreads();

    float acc1[4][4] = {}, acc2[4][4] = {};
#pragma unroll 4
    for (int k = 0; k < 64; k++) {
        float a[4];
#pragma unroll
        for (int q = 0; q < 4; q++) a[q] = As[(ty * 4 + q) * 64 + k];
        float4 b1 = *(float4*)&Ws1[k * 64 + tx * 4];
        float4 b2 = *(float4*)&Ws2[k * 64 + tx * 4];
#pragma unroll
        for (int q = 0; q < 4; q++) {
            acc1[q][0] += a[q] * b1.x; acc1[q][1] += a[q] * b1.y;
            acc1[q][2] += a[q] * b1.z; acc1[q][3] += a[q] * b1.w;
            acc2[q][0] += a[q] * b2.x; acc2[q][1] += a[q] * b2.y;
            acc2[q][2] += a[q] * b2.z; acc2[q][3] += a[q] * b2.w;
        }
    }
#pragma unroll
    for (int q = 0; q < 4; q++) {
        int row = t0 + ty * 4 + q;
        float4 v1 = make_float4(silu_f(acc1[q][0]), silu_f(acc1[q][1]),
                                silu_f(acc1[q][2]), silu_f(acc1[q][3]));
        float4 v2 = make_float4(silu_f(acc2[q][0]), silu_f(acc2[q][1]),
                                silu_f(acc2[q][2]), silu_f(acc2[q][3]));
        *(float4*)&out1[row * HH + n * 64 + tx * 4] = v1;
        *(float4*)&out2[row * HH + n * 64 + tx * 4] = v2;
    }
}

// ============ block-diagonal GEMM, K=192 (wpost), silu ============
__global__ void __launch_bounds__(256)
bd192_kernel(const float* __restrict__ in, const float* __restrict__ W,
             float* __restrict__ out) {
    __shared__ float As[64 * 64];
    __shared__ float Ws[64 * 64];
    const int t0 = blockIdx.x * 64;
    const int n = blockIdx.y;
    const int tid = threadIdx.x;
    const int tx = tid & 15, ty = tid >> 4;

    float acc[4][4] = {};
    for (int c = 0; c < 3; c++) {
        for (int i = tid; i < 1024; i += 256) {
            int t = i >> 4, kc = (i & 15) << 2;
            *(float4*)&As[t * 64 + kc] =
                *(const float4*)&in[(t0 + t) * 3 * DD + n * 192 + c * 64 + kc];
        }
        for (int i = tid; i < 1024; i += 256) {
            int o = i >> 4, kc = (i & 15) << 2;
            float4 w = *(const float4*)&W[(n * 64 + o) * 192 + c * 64 + kc];
            Ws[(kc + 0) * 64 + o] = w.x; Ws[(kc + 1) * 64 + o] = w.y;
            Ws[(kc + 2) * 64 + o] = w.z; Ws[(kc + 3) * 64 + o] = w.w;
        }
        __syncthreads();
#pragma unroll 4
        for (int k = 0; k < 64; k++) {
            float a[4];
#pragma unroll
            for (int q = 0; q < 4; q++) a[q] = As[(ty * 4 + q) * 64 + k];
            float4 b = *(float4*)&Ws[k * 64 + tx * 4];
#pragma unroll
            for (int q = 0; q < 4; q++) {
                acc[q][0] += a[q] * b.x; acc[q][1] += a[q] * b.y;
                acc[q][2] += a[q] * b.z; acc[q][3] += a[q] * b.w;
            }
        }
        __syncthreads();
    }
#pragma unroll
    for (int q = 0; q < 4; q++) {
        int row = t0 + ty * 4 + q;
        float4 v = make_float4(silu_f(acc[q][0]), silu_f(acc[q][1]),
                               silu_f(acc[q][2]), silu_f(acc[q][3]));
        *(float4*)&out[row * HH + n * 64 + tx * 4] = v;
    }
}

// ============ residual update: x += blockdiag(r, wlocal) + tmp @ lowA^T ============
__global__ void __launch_bounds__(256)
update_kernel(float* __restrict__ x, const float* __restrict__ r,
              const float* __restrict__ tmp, const float* __restrict__ wlocal,
              const float* __restrict__ lowA) {
    __shared__ float As[64 * 64];
    __shared__ float Ws[64 * 64];
    const int t0 = blockIdx.x * 64;
    const int n = blockIdx.y;
    const int tid = threadIdx.x;
    const int tx = tid & 15, ty = tid >> 4;

    float acc[4][4] = {};
    // phase 1: wlocal (K=64 over r block n)
    for (int i = tid; i < 1024; i += 256) {
        int t = i >> 4, kc = (i & 15) << 2;
        *(float4*)&As[t * 64 + kc] = *(const float4*)&r[(t0 + t) * HH + n * 64 + kc];
    }
    for (int i = tid; i < 1024; i += 256) {
        int o = i >> 4, kc = (i & 15) << 2;
        float4 w = *(const float4*)&wlocal[(n * 64 + o) * 64 + kc];
        Ws[(kc + 0) * 64 + o] = w.x; Ws[(kc + 1) * 64 + o] = w.y;
        Ws[(kc + 2) * 64 + o] = w.z; Ws[(kc + 3) * 64 + o] = w.w;
    }
    __syncthreads();
#pragma unroll 4
    for (int k = 0; k < 64; k++) {
        float a[4];
#pragma unroll
        for (int q = 0; q < 4; q++) a[q] = As[(ty * 4 + q) * 64 + k];
        float4 b = *(float4*)&Ws[k * 64 + tx * 4];
#pragma unroll
        for (int q = 0; q < 4; q++) {
            acc[q][0] += a[q] * b.x; acc[q][1] += a[q] * b.y;
            acc[q][2] += a[q] * b.z; acc[q][3] += a[q] * b.w;
        }
    }
    __syncthreads();
    // phase 2: lowA (K=64 over tmp)
    for (int i = tid; i < 1024; i += 256) {
        int t = i >> 4, kc = (i & 15) << 2;
        *(float4*)&As[t * 64 + kc] = *(const float4*)&tmp[(t0 + t) * RANKK + kc];
    }
    for (int i = tid; i < 1024; i += 256) {
        int o = i >> 4, kc = (i & 15) << 2;
        float4 w = *(const float4*)&lowA[(n * 64 + o) * RANKK + kc];
        Ws[(kc + 0) * 64 + o] = w.x; Ws[(kc + 1) * 64 + o] = w.y;
        Ws[(kc + 2) * 64 + o] = w.z; Ws[(kc + 3) * 64 + o] = w.w;
    }
    __syncthreads();
#pragma unroll 4
    for (int k = 0; k < 64; k++) {
        float a[4];
#pragma unroll
        for (int q = 0; q < 4; q++) a[q] = As[(ty * 4 + q) * 64 + k];
        float4 b = *(float4*)&Ws[k * 64 + tx * 4];
#pragma unroll
        for (int q = 0; q < 4; q++) {
            acc[q][0] += a[q] * b.x; acc[q][1] += a[q] * b.y;
            acc[q][2] += a[q] * b.z; acc[q][3] += a[q] * b.w;
        }
    }
#pragma unroll
    for (int q = 0; q < 4; q++) {
        int row = t0 + ty * 4 + q;
        float4* px = (float4*)&x[row * DD + n * 64 + tx * 4];
        float4 v = *px;
        v.x += acc[q][0]; v.y += acc[q][1]; v.z += acc[q][2]; v.w += acc[q][3];
        *px = v;
    }
}

// ============ lowrank stage 1: tmp[2048,64] = r[2048,1024] @ lowB^T ============
// grid TT/16, block 256. Thread: 1 t-row, 4 outputs.
__global__ void __launch_bounds__(256)
lowrank1_kernel(const float* __restrict__ r, const float* __restrict__ lowB,
                float* __restrict__ tmp) {
    __shared__ float As[16 * 64];
    __shared__ float Ws[64 * 64];
    const int t0 = blockIdx.x * 16;
    const int tid = threadIdx.x;
    const int tx = tid & 15, ty = tid >> 4;  // ty = t (0..15), tx*4 = o
    float acc[4] = {};
    for (int c = 0; c < 16; c++) {
        {
            int t = tid >> 4, kc = (tid & 15) << 2;
            *(float4*)&As[t * 64 + kc] = *(const float4*)&r[(t0 + t) * HH + c * 64 + kc];
        }
        for (int i = tid; i < 1024; i += 256) {
            int o = i >> 4, kc = (i & 15) << 2;
            float4 w = *(const float4*)&lowB[o * HH + c * 64 + kc];
            Ws[(kc + 0) * 64 + o] = w.x; Ws[(kc + 1) * 64 + o] = w.y;
            Ws[(kc + 2) * 64 + o] = w.z; Ws[(kc + 3) * 64 + o] = w.w;
        }
        __syncthreads();
#pragma unroll 8
        for (int k = 0; k < 64; k++) {
            float a = As[ty * 64 + k];
            float4 b = *(float4*)&Ws[k * 64 + tx * 4];
            acc[0] += a * b.x; acc[1] += a * b.y; acc[2] += a * b.z; acc[3] += a * b.w;
        }
        __syncthreads();
    }
    *(float4*)&tmp[(t0 + ty) * RANKK + tx * 4] = make_float4(acc[0], acc[1], acc[2], acc[3]);
}

// ============ causal scan, 3-phase chunked ============
__global__ void scanA_kernel(float* __restrict__ buf, const float* __restrict__ logA,
                             const float* __restrict__ logdt, float* __restrict__ seg) {
    int d = blockIdx.x * 32 + threadIdx.x;
    int s = blockIdx.y * 8 + threadIdx.y;
    float a = expf(-expf(logA[d]) * expf(logdt[d]));
    float y = 0.f;
    int t0 = s * SEGLEN;
#pragma unroll 8
    for (int tt = 0; tt < SEGLEN; tt++) {
        int i = (t0 + tt) * DD + d;
        y = a * y + buf[i];
        buf[i] = y;
    }
    seg[s * DD + d] = y;
}

__global__ void scanB_kernel(float* __restrict__ seg, const float* __restrict__ logA,
                             const float* __restrict__ logdt) {
    int d = blockIdx.x * 16 + threadIdx.x;
    int j = threadIdx.y;  // 0..63
    float a = expf(-expf(logA[d]) * expf(logdt[d]));
    float a32 = a;
#pragma unroll
    for (int q = 0; q < 5; q++) a32 *= a32;
    __shared__ float s[NSEG][17];
    float cur = seg[j * DD + d];
    s[j][threadIdx.x] = cur;
    float m = a32;
    for (int st = 1; st < NSEG; st <<= 1) {
        __syncthreads();
        float prev = (j >= st) ? s[j - st][threadIdx.x] : 0.f;
        __syncthreads();
        cur += m * prev;
        s[j][threadIdx.x] = cur;
        m = m * m;
    }
    seg[j * DD + d] = cur;
}

__global__ void scanC_kernel(float* __restrict__ buf, const float* __restrict__ logA,
                             const float* __restrict__ logdt, const float* __restrict__ seg) {
    int d = blockIdx.x * 32 + threadIdx.x;
    int s = blockIdx.y * 8 + threadIdx.y;
    if (s == 0) return;
    float a = expf(-expf(logA[d]) * expf(logdt[d]));
    float carry = seg[(s - 1) * DD + d];
    float f = a;
    int t0 = s * SEGLEN;
#pragma unroll 8
    for (int tt = 0; tt < SEGLEN; tt++) {
        int i = (t0 + tt) * DD + d;
        buf[i] += f * carry;
        f *= a;
    }
}

// ---------------- h = h_seq + gain*u_dep ; rmsnorm(h) ; build concat ----------------
__global__ void combine_prep_kernel(const float* __restrict__ hseq, const float* __restrict__ udep,
                                    const float* __restrict__ e, const float* __restrict__ logAd,
                                    const float* __restrict__ logdtd, const int* __restrict__ pK,
                                    float* __restrict__ c) {
    int t = blockIdx.x;
    int tid = threadIdx.x;
    int K = *pK;
    float hv[4];
    float ss = 0.f;
#pragma unroll
    for (int r = 0; r < 4; r++) {
        int d = tid + r * 256;
        float g;
        if (d < NMEM) {
            g = (float)K;
        } else {
            float aD = expf(-expf(logAd[d - NMEM]) * expf(logdtd[d - NMEM]));
            float om = 1.f - aD;
            float safe = fmaxf(om, 1e-8f);
            float p = 1.f;
            for (int k = 0; k < K; k++) p *= aD;
            g = (fabsf(om) < 1e-6f) ? (float)K : (1.f - p) / safe;
        }
        float h = hseq[t * DD + d] + g * udep[t * DD + d];
        hv[r] = h;
        ss += h * h;
    }
    __shared__ float red[256];
    red[tid] = ss;
    __syncthreads();
    for (int s = 128; s > 0; s >>= 1) {
        if (tid < s) red[tid] += red[tid + s];
        __syncthreads();
    }
    float sc = rsqrtf(red[0] / (float)DD + RMS_EPS);
#pragma unroll
    for (int r = 0; r < 4; r++) {
        int d = tid + r * 256;
        c[t * 3 * DD + d] = hv[r] * sc;
        c[t * 3 * DD + DD + d] = e[t * DD + d];
        c[t * 3 * DD + 2 * DD + d] = (t > 0) ? e[(t - 1) * DD + d] : 0.f;
    }
}

// ---------------- LM head GEMM: C[2048,50304] = A[2048,1024] * B[50304,1024]^T ----------------
#define MMA_TF32(c, a, b)                                                              \
    asm volatile(                                                                      \
        "mma.sync.aligned.m16n8k8.row.col.f32.tf32.tf32.f32 "                          \
        "{%0,%1,%2,%3},{%4,%5,%6,%7},{%8,%9},{%0,%1,%2,%3};\n"                         \
        : "+f"(c[0]), "+f"(c[1]), "+f"(c[2]), "+f"(c[3])                               \
        : "r"(a[0]), "r"(a[1]), "r"(a[2]), "r"(a[3]), "r"(b[0]), "r"(b[1]))

__global__ void __launch_bounds__(256, 2)
lmhead_gemm(const float* __restrict__ A, const float* __restrict__ B, float* __restrict__ C) {
    __shared__ float As[2][16][132];
    __shared__ float Bs[2][16][132];
    const int bm = blockIdx.y * 128;
    const int bn = blockIdx.x * 128;
    const int tid = threadIdx.x;
    const int lane = tid & 31;
    const int warp = tid >> 5;
    const int wm = (warp >> 2) * 64;
    const int wn = (warp & 3) * 32;

    float acc[4][4][4];
#pragma unroll
    for (int i = 0; i < 4; i++)
#pragma unroll
        for (int j = 0; j < 4; j++)
#pragma unroll
            for (int k = 0; k < 4; k++) acc[i][j][k] = 0.f;

    const int lin0 = tid, lin1 = tid + 256;
    const int m0 = lin0 >> 2, kk0 = (lin0 & 3) << 2;
    const int m1 = lin1 >> 2, kk1 = (lin1 & 3) << 2;

    float4 la0, la1, lb0, lb1;
#define G_LOAD(kt)                                                            \
    {                                                                         \
        la0 = *(const float4*)(A + (bm + m0) * DD + (kt) * 16 + kk0);         \
        la1 = *(const float4*)(A + (bm + m1) * DD + (kt) * 16 + kk1);         \
        lb0 = *(const float4*)(B + (size_t)(bn + m0) * DD + (kt) * 16 + kk0); \
        lb1 = *(const float4*)(B + (size_t)(bn + m1) * DD + (kt) * 16 + kk1); \
    }
#define S_STORE(buf)                                                          \
    {                                                                         \
        As[buf][kk0 + 0][m0] = tf32r(la0.x); As[buf][kk0 + 1][m0] = tf32r(la0.y); \
        As[buf][kk0 + 2][m0] = tf32r(la0.z); As[buf][kk0 + 3][m0] = tf32r(la0.w); \
        As[buf][kk1 + 0][m1] = tf32r(la1.x); As[buf][kk1 + 1][m1] = tf32r(la1.y); \
        As[buf][kk1 + 2][m1] = tf32r(la1.z); As[buf][kk1 + 3][m1] = tf32r(la1.w); \
        Bs[buf][kk0 + 0][m0] = tf32r(lb0.x); Bs[buf][kk0 + 1][m0] = tf32r(lb0.y); \
        Bs[buf][kk0 + 2][m0] = tf32r(lb0.z); Bs[buf][kk0 + 3][m0] = tf32r(lb0.w); \
        Bs[buf][kk1 + 0][m1] = tf32r(lb1.x); Bs[buf][kk1 + 1][m1] = tf32r(lb1.y); \
        Bs[buf][kk1 + 2][m1] = tf32r(lb1.z); Bs[buf][kk1 + 3][m1] = tf32r(lb1.w); \
    }

    G_LOAD(0);
    S_STORE(0);
    __syncthreads();

    const int rr = lane >> 2;
    const int kc = lane & 3;
    const int NK = DD / 16;

    for (int kt = 0; kt < NK; kt++) {
        int cur = kt & 1;
        if (kt + 1 < NK) G_LOAD(kt + 1);
#pragma unroll
        for (int ks = 0; ks < 16; ks += 8) {
            unsigned af[4][4], bf[4][2];
#pragma unroll
            for (int mi = 0; mi < 4; mi++) {
                af[mi][0] = __float_as_uint(As[cur][ks + kc][wm + mi * 16 + rr]);
                af[mi][1] = __float_as_uint(As[cur][ks + kc][wm + mi * 16 + rr + 8]);
                af[mi][2] = __float_as_uint(As[cur][ks + kc + 4][wm + mi * 16 + rr]);
                af[mi][3] = __float_as_uint(As[cur][ks + kc + 4][wm + mi * 16 + rr + 8]);
            }
#pragma unroll
            for (int nj = 0; nj < 4; nj++) {
                bf[nj][0] = __float_as_uint(Bs[cur][ks + kc][wn + nj * 8 + rr]);
                bf[nj][1] = __float_as_uint(Bs[cur][ks + kc + 4][wn + nj * 8 + rr]);
            }
#pragma unroll
            for (int mi = 0; mi < 4; mi++)
#pragma unroll
                for (int nj = 0; nj < 4; nj++) MMA_TF32(acc[mi][nj], af[mi], bf[nj]);
        }
        if (kt + 1 < NK) {
            S_STORE(cur ^ 1);
            __syncthreads();
        }
    }

#pragma unroll
    for (int mi = 0; mi < 4; mi++) {
#pragma unroll
        for (int nj = 0; nj < 4; nj++) {
            int r0 = bm + wm + mi * 16 + rr;
            int c0 = bn + wn + nj * 8 + (kc << 1);
            float2 v0 = make_float2(acc[mi][nj][0], acc[mi][nj][1]);
            float2 v1 = make_float2(acc[mi][nj][2], acc[mi][nj][3]);
            *(float2*)(C + (size_t)r0 * VV + c0) = v0;
            *(float2*)(C + (size_t)(r0 + 8) * VV + c0) = v1;
        }
    }
}

// ---------------- launcher ----------------
extern "C" void kernel_launch(void* const* d_in, const int* in_sizes, int n_in,
                              void* d_out, int out_size) {
    const int* idx = (const int*)d_in[0];
    const int* pK = (const int*)d_in[1];
    const float* wte = (const float*)d_in[2];
    const float* wpe = (const float*)d_in[3];
    const float* bseq_w = (const float*)d_in[4];
    const float* logA_seq = (const float*)d_in[5];
    const float* logdt_seq = (const float*)d_in[6];
    const float* bdepth_w = (const float*)d_in[7];
    const float* logA_depth = (const float*)d_in[8];
    const float* logdt_depth = (const float*)d_in[9];
    const float* wpost_w = (const float*)d_in[10];
    const float* wlocal_w = (const float*)d_in[11];
    const float* lowA = (const float*)d_in[12];
    const float* lowB = (const float*)d_in[13];
    const float* lm_head_w = (const float*)d_in[14];
    float* out = (float*)d_out;

    float *x, *e, *h, *ud, *c, *r, *tmp, *xn, *seg;
    cudaGetSymbolAddress((void**)&x, g_x);
    cudaGetSymbolAddress((void**)&e, g_e);
    cudaGetSymbolAddress((void**)&h, g_h);
    cudaGetSymbolAddress((void**)&ud, g_ud);
    cudaGetSymbolAddress((void**)&c, g_c);
    cudaGetSymbolAddress((void**)&r, g_r);
    cudaGetSymbolAddress((void**)&tmp, g_tmp);
    cudaGetSymbolAddress((void**)&xn, g_xn);
    cudaGetSymbolAddress((void**)&seg, g_seg);

    embed_kernel<<<TT, 256>>>(idx, wte, wpe, x);

    for (int l = 0; l < LYR; l++) {
        const float* bseq_l = bseq_w + l * NBLK * 64 * 64;
        const float* lAs = logA_seq + l * HH;
        const float* lDs = logdt_seq + l * HH;
        const float* bdep_l = bdepth_w + l * NBLK * 64 * 64;
        const float* lAd = logA_depth + l * (HH - NMEM);
        const float* lDd = logdt_depth + l * (HH - NMEM);
        const float* wpost_l = wpost_w + l * NBLK * 64 * 192;
        const float* wlocal_l = wlocal_w + l * NBLK * 64 * 64;
        const float* lowA_l = lowA + l * DD * RANKK;
        const float* lowB_l = lowB + l * RANKK * HH;

        rmsnorm_kernel<<<TT, 256>>>(x, e);
        bd64_dual_kernel<<<dim3(TT / 64, NBLK), 256>>>(e, bseq_l, bdep_l, h, ud);
        scanA_kernel<<<dim3(32, 8), dim3(32, 8)>>>(h, lAs, lDs, seg);
        scanB_kernel<<<DD / 16, dim3(16, NSEG)>>>(seg, lAs, lDs);
        scanC_kernel<<<dim3(32, 8), dim3(32, 8)>>>(h, lAs, lDs, seg);
        combine_prep_kernel<<<TT, 256>>>(h, ud, e, lAd, lDd, pK, c);
        bd192_kernel<<<dim3(TT / 64, NBLK), 256>>>(c, wpost_l, r);
        lowrank1_kernel<<<TT / 16, 256>>>(r, lowB_l, tmp);
        update_kernel<<<dim3(TT / 64, NBLK), 256>>>(x, r, tmp, wlocal_l, lowA_l);
    }

    rmsnorm_kernel<<<TT, 256>>>(x, xn);
    lmhead_gemm<<<dim3(VV / 128, TT / 128), 256>>>(xn, lm_head_w, out);
}

// round 4
// speedup vs baseline: 1.0009x; 1.0009x over previous
#include <cuda_runtime.h>
#include <cuda_bf16.h>
#include <math.h>

#define TT 2048
#define DD 1024
#define HH 1024
#define NBLK 16
#define LYR 4
#define RANKK 64
#define NMEM 64
#define VV 50304
#define RMS_EPS 1.1920929e-7f
#define SEGLEN 32
#define NSEG 64

// ---------------- scratch (static device arrays; no allocation) ----------------
__device__ float g_x[TT * DD];
__device__ float g_e[TT * DD];
__device__ float g_h[TT * DD];     // drive_seq -> h_seq (scan in place)
__device__ float g_ud[TT * DD];    // depth drive
__device__ float g_c[TT * 3 * DD]; // concat [hn, e, shifted]
__device__ float g_r[TT * DD];
__device__ float g_tmp[TT * RANKK];
__device__ float g_xn[TT * DD];
__device__ float g_seg[NSEG * DD];

// ---------------- helpers ----------------
__device__ __forceinline__ float silu_f(float x) { return x / (1.0f + expf(-x)); }

__device__ __forceinline__ float tf32r(float x) {
    unsigned u;
    asm("cvt.rna.tf32.f32 %0, %1;" : "=r"(u) : "f"(x));
    return __uint_as_float(u);
}

// ---------------- embedding ----------------
__global__ void embed_kernel(const int* __restrict__ idx, const float* __restrict__ wte,
                             const float* __restrict__ wpe, float* __restrict__ x) {
    int t = blockIdx.x;
    int row = idx[t];
    const float4* wrow = (const float4*)(wte + (long)row * DD);
    const float4* prow = (const float4*)(wpe + (long)t * DD);
    float4* xo = (float4*)(x + t * DD);
    for (int d = threadIdx.x; d < DD / 4; d += blockDim.x) {
        float4 a = wrow[d], b = prow[d];
        xo[d] = make_float4(a.x + b.x, a.y + b.y, a.z + b.z, a.w + b.w);
    }
}

// ---------------- rmsnorm ----------------
__global__ void rmsnorm_kernel(const float* __restrict__ in, float* __restrict__ out) {
    int t = blockIdx.x;
    int tid = threadIdx.x;
    float4 v = ((const float4*)(in + t * DD))[tid];
    float ss = v.x * v.x + v.y * v.y + v.z * v.z + v.w * v.w;
    __shared__ float red[256];
    red[tid] = ss;
    __syncthreads();
    for (int s = 128; s > 0; s >>= 1) {
        if (tid < s) red[tid] += red[tid + s];
        __syncthreads();
    }
    float sc = rsqrtf(red[0] / (float)DD + RMS_EPS);
    ((float4*)(out + t * DD))[tid] = make_float4(v.x * sc, v.y * sc, v.z * sc, v.w * sc);
}

// ============ dual block-diagonal GEMM, K=64, silu: h=silu(e@W1^T), ud=silu(e@W2^T) =======
// grid (TT/64, NBLK), block 256. Output tile [64 t][64 o] for block n, for BOTH weights.
__global__ void __launch_bounds__(256)
bd64_dual_kernel(const float* __restrict__ in, const float* __restrict__ W1,
                 const float* __restrict__ W2, float* __restrict__ out1,
                 float* __restrict__ out2) {
    __shared__ float As[64 * 64];   // [t][k]
    __shared__ float Ws1[64 * 64];  // [k][o]
    __shared__ float Ws2[64 * 64];
    const int t0 = blockIdx.x * 64;
    const int n = blockIdx.y;
    const int tid = threadIdx.x;
    const int tx = tid & 15, ty = tid >> 4;

    for (int i = tid; i < 1024; i += 256) {
        int t = i >> 4, kc = (i & 15) << 2;
        *(float4*)&As[t * 64 + kc] = *(const float4*)&in[(t0 + t) * DD + n * 64 + kc];
    }
    for (int i = tid; i < 1024; i += 256) {
        int o = i >> 4, kc = (i & 15) << 2;
        float4 w = *(const float4*)&W1[(n * 64 + o) * 64 + kc];
        Ws1[(kc + 0) * 64 + o] = w.x; Ws1[(kc + 1) * 64 + o] = w.y;
        Ws1[(kc + 2) * 64 + o] = w.z; Ws1[(kc + 3) * 64 + o] = w.w;
        float4 u = *(const float4*)&W2[(n * 64 + o) * 64 + kc];
        Ws2[(kc + 0) * 64 + o] = u.x; Ws2[(kc + 1) * 64 + o] = u.y;
        Ws2[(kc + 2) * 64 + o] = u.z; Ws2[(kc + 3) * 64 + o] = u.w;
    }
    __syncthreads();

    float acc1[4][4] = {}, acc2[4][4] = {};
#pragma unroll 4
    for (int k = 0; k < 64; k++) {
        float a[4];
#pragma unroll
        for (int q = 0; q < 4; q++) a[q] = As[(ty * 4 + q) * 64 + k];
        float4 b1 = *(float4*)&Ws1[k * 64 + tx * 4];
        float4 b2 = *(float4*)&Ws2[k * 64 + tx * 4];
#pragma unroll
        for (int q = 0; q < 4; q++) {
            acc1[q][0] += a[q] * b1.x; acc1[q][1] += a[q] * b1.y;
            acc1[q][2] += a[q] * b1.z; acc1[q][3] += a[q] * b1.w;
            acc2[q][0] += a[q] * b2.x; acc2[q][1] += a[q] * b2.y;
            acc2[q][2] += a[q] * b2.z; acc2[q][3] += a[q] * b2.w;
        }
    }
#pragma unroll
    for (int q = 0; q < 4; q++) {
        int row = t0 + ty * 4 + q;
        float4 v1 = make_float4(silu_f(acc1[q][0]), silu_f(acc1[q][1]),
                                silu_f(acc1[q][2]), silu_f(acc1[q][3]));
        float4 v2 = make_float4(silu_f(acc2[q][0]), silu_f(acc2[q][1]),
                                silu_f(acc2[q][2]), silu_f(acc2[q][3]));
        *(float4*)&out1[row * HH + n * 64 + tx * 4] = v1;
        *(float4*)&out2[row * HH + n * 64 + tx * 4] = v2;
    }
}

// ============ block-diagonal GEMM, K=192 (wpost), silu ============
__global__ void __launch_bounds__(256)
bd192_kernel(const float* __restrict__ in, const float* __restrict__ W,
             float* __restrict__ out) {
    __shared__ float As[64 * 64];
    __shared__ float Ws[64 * 64];
    const int t0 = blockIdx.x * 64;
    const int n = blockIdx.y;
    const int tid = threadIdx.x;
    const int tx = tid & 15, ty = tid >> 4;

    float acc[4][4] = {};
    for (int c = 0; c < 3; c++) {
        for (int i = tid; i < 1024; i += 256) {
            int t = i >> 4, kc = (i & 15) << 2;
            *(float4*)&As[t * 64 + kc] =
                *(const float4*)&in[(t0 + t) * 3 * DD + n * 192 + c * 64 + kc];
        }
        for (int i = tid; i < 1024; i += 256) {
            int o = i >> 4, kc = (i & 15) << 2;
            float4 w = *(const float4*)&W[(n * 64 + o) * 192 + c * 64 + kc];
            Ws[(kc + 0) * 64 + o] = w.x; Ws[(kc + 1) * 64 + o] = w.y;
            Ws[(kc + 2) * 64 + o] = w.z; Ws[(kc + 3) * 64 + o] = w.w;
        }
        __syncthreads();
#pragma unroll 4
        for (int k = 0; k < 64; k++) {
            float a[4];
#pragma unroll
            for (int q = 0; q < 4; q++) a[q] = As[(ty * 4 + q) * 64 + k];
            float4 b = *(float4*)&Ws[k * 64 + tx * 4];
#pragma unroll
            for (int q = 0; q < 4; q++) {
                acc[q][0] += a[q] * b.x; acc[q][1] += a[q] * b.y;
                acc[q][2] += a[q] * b.z; acc[q][3] += a[q] * b.w;
            }
        }
        __syncthreads();
    }
#pragma unroll
    for (int q = 0; q < 4; q++) {
        int row = t0 + ty * 4 + q;
        float4 v = make_float4(silu_f(acc[q][0]), silu_f(acc[q][1]),
                               silu_f(acc[q][2]), silu_f(acc[q][3]));
        *(float4*)&out[row * HH + n * 64 + tx * 4] = v;
    }
}

// ============ residual update: x += blockdiag(r, wlocal) + tmp @ lowA^T ============
__global__ void __launch_bounds__(256)
update_kernel(float* __restrict__ x, const float* __restrict__ r,
              const float* __restrict__ tmp, const float* __restrict__ wlocal,
              const float* __restrict__ lowA) {
    __shared__ float As[64 * 64];
    __shared__ float Ws[64 * 64];
    const int t0 = blockIdx.x * 64;
    const int n = blockIdx.y;
    const int tid = threadIdx.x;
    const int tx = tid & 15, ty = tid >> 4;

    float acc[4][4] = {};
    // phase 1: wlocal (K=64 over r block n)
    for (int i = tid; i < 1024; i += 256) {
        int t = i >> 4, kc = (i & 15) << 2;
        *(float4*)&As[t * 64 + kc] = *(const float4*)&r[(t0 + t) * HH + n * 64 + kc];
    }
    for (int i = tid; i < 1024; i += 256) {
        int o = i >> 4, kc = (i & 15) << 2;
        float4 w = *(const float4*)&wlocal[(n * 64 + o) * 64 + kc];
        Ws[(kc + 0) * 64 + o] = w.x; Ws[(kc + 1) * 64 + o] = w.y;
        Ws[(kc + 2) * 64 + o] = w.z; Ws[(kc + 3) * 64 + o] = w.w;
    }
    __syncthreads();
#pragma unroll 4
    for (int k = 0; k < 64; k++) {
        float a[4];
#pragma unroll
        for (int q = 0; q < 4; q++) a[q] = As[(ty * 4 + q) * 64 + k];
        float4 b = *(float4*)&Ws[k * 64 + tx * 4];
#pragma unroll
        for (int q = 0; q < 4; q++) {
            acc[q][0] += a[q] * b.x; acc[q][1] += a[q] * b.y;
            acc[q][2] += a[q] * b.z; acc[q][3] += a[q] * b.w;
        }
    }
    __syncthreads();
    // phase 2: lowA (K=64 over tmp)
    for (int i = tid; i < 1024; i += 256) {
        int t = i >> 4, kc = (i & 15) << 2;
        *(float4*)&As[t * 64 + kc] = *(const float4*)&tmp[(t0 + t) * RANKK + kc];
    }
    for (int i = tid; i < 1024; i += 256) {
        int o = i >> 4, kc = (i & 15) << 2;
        float4 w = *(const float4*)&lowA[(n * 64 + o) * RANKK + kc];
        Ws[(kc + 0) * 64 + o] = w.x; Ws[(kc + 1) * 64 + o] = w.y;
        Ws[(kc + 2) * 64 + o] = w.z; Ws[(kc + 3) * 64 + o] = w.w;
    }
    __syncthreads();
#pragma unroll 4
    for (int k = 0; k < 64; k++) {
        float a[4];
#pragma unroll
        for (int q = 0; q < 4; q++) a[q] = As[(ty * 4 + q) * 64 + k];
        float4 b = *(float4*)&Ws[k * 64 + tx * 4];
#pragma unroll
        for (int q = 0; q < 4; q++) {
            acc[q][0] += a[q] * b.x; acc[q][1] += a[q] * b.y;
            acc[q][2] += a[q] * b.z; acc[q][3] += a[q] * b.w;
        }
    }
#pragma unroll
    for (int q = 0; q < 4; q++) {
        int row = t0 + ty * 4 + q;
        float4* px = (float4*)&x[row * DD + n * 64 + tx * 4];
        float4 v = *px;
        v.x += acc[q][0]; v.y += acc[q][1]; v.z += acc[q][2]; v.w += acc[q][3];
        *px = v;
    }
}

// ============ lowrank stage 1: tmp[2048,64] = r[2048,1024] @ lowB^T ============
// grid TT/16, block 256. Thread: 1 t-row, 4 outputs.
__global__ void __launch_bounds__(256)
lowrank1_kernel(const float* __restrict__ r, const float* __restrict__ lowB,
                float* __restrict__ tmp) {
    __shared__ float As[16 * 64];
    __shared__ float Ws[64 * 64];
    const int t0 = blockIdx.x * 16;
    const int tid = threadIdx.x;
    const int tx = tid & 15, ty = tid >> 4;  // ty = t (0..15), tx*4 = o
    float acc[4] = {};
    for (int c = 0; c < 16; c++) {
        {
            int t = tid >> 4, kc = (tid & 15) << 2;
            *(float4*)&As[t * 64 + kc] = *(const float4*)&r[(t0 + t) * HH + c * 64 + kc];
        }
        for (int i = tid; i < 1024; i += 256) {
            int o = i >> 4, kc = (i & 15) << 2;
            float4 w = *(const float4*)&lowB[o * HH + c * 64 + kc];
            Ws[(kc + 0) * 64 + o] = w.x; Ws[(kc + 1) * 64 + o] = w.y;
            Ws[(kc + 2) * 64 + o] = w.z; Ws[(kc + 3) * 64 + o] = w.w;
        }
        __syncthreads();
#pragma unroll 8
        for (int k = 0; k < 64; k++) {
            float a = As[ty * 64 + k];
            float4 b = *(float4*)&Ws[k * 64 + tx * 4];
            acc[0] += a * b.x; acc[1] += a * b.y; acc[2] += a * b.z; acc[3] += a * b.w;
        }
        __syncthreads();
    }
    *(float4*)&tmp[(t0 + ty) * RANKK + tx * 4] = make_float4(acc[0], acc[1], acc[2], acc[3]);
}

// ============ causal scan, 3-phase chunked ============
__global__ void scanA_kernel(float* __restrict__ buf, const float* __restrict__ logA,
                             const float* __restrict__ logdt, float* __restrict__ seg) {
    int d = blockIdx.x * 32 + threadIdx.x;
    int s = blockIdx.y * 8 + threadIdx.y;
    float a = expf(-expf(logA[d]) * expf(logdt[d]));
    float y = 0.f;
    int t0 = s * SEGLEN;
#pragma unroll 8
    for (int tt = 0; tt < SEGLEN; tt++) {
        int i = (t0 + tt) * DD + d;
        y = a * y + buf[i];
        buf[i] = y;
    }
    seg[s * DD + d] = y;
}

__global__ void scanB_kernel(float* __restrict__ seg, const float* __restrict__ logA,
                             const float* __restrict__ logdt) {
    int d = blockIdx.x * 16 + threadIdx.x;
    int j = threadIdx.y;  // 0..63
    float a = expf(-expf(logA[d]) * expf(logdt[d]));
    float a32 = a;
#pragma unroll
    for (int q = 0; q < 5; q++) a32 *= a32;
    __shared__ float s[NSEG][17];
    float cur = seg[j * DD + d];
    s[j][threadIdx.x] = cur;
    float m = a32;
    for (int st = 1; st < NSEG; st <<= 1) {
        __syncthreads();
        float prev = (j >= st) ? s[j - st][threadIdx.x] : 0.f;
        __syncthreads();
        cur += m * prev;
        s[j][threadIdx.x] = cur;
        m = m * m;
    }
    seg[j * DD + d] = cur;
}

__global__ void scanC_kernel(float* __restrict__ buf, const float* __restrict__ logA,
                             const float* __restrict__ logdt, const float* __restrict__ seg) {
    int d = blockIdx.x * 32 + threadIdx.x;
    int s = blockIdx.y * 8 + threadIdx.y;
    if (s == 0) return;
    float a = expf(-expf(logA[d]) * expf(logdt[d]));
    float carry = seg[(s - 1) * DD + d];
    float f = a;
    int t0 = s * SEGLEN;
#pragma unroll 8
    for (int tt = 0; tt < SEGLEN; tt++) {
        int i = (t0 + tt) * DD + d;
        buf[i] += f * carry;
        f *= a;
    }
}

// ---------------- h = h_seq + gain*u_dep ; rmsnorm(h) ; build concat ----------------
__global__ void combine_prep_kernel(const float* __restrict__ hseq, const float* __restrict__ udep,
                                    const float* __restrict__ e, const float* __restrict__ logAd,
                                    const float* __restrict__ logdtd, const int* __restrict__ pK,
                                    float* __restrict__ c) {
    int t = blockIdx.x;
    int tid = threadIdx.x;
    int K = *pK;
    float hv[4];
    float ss = 0.f;
#pragma unroll
    for (int r = 0; r < 4; r++) {
        int d = tid + r * 256;
        float g;
        if (d < NMEM) {
            g = (float)K;
        } else {
            float aD = expf(-expf(logAd[d - NMEM]) * expf(logdtd[d - NMEM]));
            float om = 1.f - aD;
            float safe = fmaxf(om, 1e-8f);
            float p = 1.f;
            for (int k = 0; k < K; k++) p *= aD;
            g = (fabsf(om) < 1e-6f) ? (float)K : (1.f - p) / safe;
        }
        float h = hseq[t * DD + d] + g * udep[t * DD + d];
        hv[r] = h;
        ss += h * h;
    }
    __shared__ float red[256];
    red[tid] = ss;
    __syncthreads();
    for (int s = 128; s > 0; s >>= 1) {
        if (tid < s) red[tid] += red[tid + s];
        __syncthreads();
    }
    float sc = rsqrtf(red[0] / (float)DD + RMS_EPS);
#pragma unroll
    for (int r = 0; r < 4; r++) {
        int d = tid + r * 256;
        c[t * 3 * DD + d] = hv[r] * sc;
        c[t * 3 * DD + DD + d] = e[t * DD + d];
        c[t * 3 * DD + 2 * DD + d] = (t > 0) ? e[(t - 1) * DD + d] : 0.f;
    }
}

// ---------------- LM head GEMM: C[2048,50304] = A[2048,1024] * B[50304,1024]^T ----------------
#define MMA_TF32(c, a, b)                                                              \
    asm volatile(                                                                      \
        "mma.sync.aligned.m16n8k8.row.col.f32.tf32.tf32.f32 "                          \
        "{%0,%1,%2,%3},{%4,%5,%6,%7},{%8,%9},{%0,%1,%2,%3};\n"                         \
        : "+f"(c[0]), "+f"(c[1]), "+f"(c[2]), "+f"(c[3])                               \
        : "r"(a[0]), "r"(a[1]), "r"(a[2]), "r"(a[3]), "r"(b[0]), "r"(b[1]))

__global__ void __launch_bounds__(256, 2)
lmhead_gemm(const float* __restrict__ A, const float* __restrict__ B, float* __restrict__ C) {
    __shared__ float As[2][16][132];
    __shared__ float Bs[2][16][132];
    const int bm = blockIdx.y * 128;
    const int bn = blockIdx.x * 128;
    const int tid = threadIdx.x;
    const int lane = tid & 31;
    const int warp = tid >> 5;
    const int wm = (warp >> 2) * 64;
    const int wn = (warp & 3) * 32;

    float acc[4][4][4];
#pragma unroll
    for (int i = 0; i < 4; i++)
#pragma unroll
        for (int j = 0; j < 4; j++)
#pragma unroll
            for (int k = 0; k < 4; k++) acc[i][j][k] = 0.f;

    const int lin0 = tid, lin1 = tid + 256;
    const int m0 = lin0 >> 2, kk0 = (lin0 & 3) << 2;
    const int m1 = lin1 >> 2, kk1 = (lin1 & 3) << 2;

    float4 la0, la1, lb0, lb1;
#define G_LOAD(kt)                                                            \
    {                                                                         \
        la0 = *(const float4*)(A + (bm + m0) * DD + (kt) * 16 + kk0);         \
        la1 = *(const float4*)(A + (bm + m1) * DD + (kt) * 16 + kk1);         \
        lb0 = *(const float4*)(B + (size_t)(bn + m0) * DD + (kt) * 16 + kk0); \
        lb1 = *(const float4*)(B + (size_t)(bn + m1) * DD + (kt) * 16 + kk1); \
    }
#define S_STORE(buf)                                                          \
    {                                                                         \
        As[buf][kk0 + 0][m0] = tf32r(la0.x); As[buf][kk0 + 1][m0] = tf32r(la0.y); \
        As[buf][kk0 + 2][m0] = tf32r(la0.z); As[buf][kk0 + 3][m0] = tf32r(la0.w); \
        As[buf][kk1 + 0][m1] = tf32r(la1.x); As[buf][kk1 + 1][m1] = tf32r(la1.y); \
        As[buf][kk1 + 2][m1] = tf32r(la1.z); As[buf][kk1 + 3][m1] = tf32r(la1.w); \
        Bs[buf][kk0 + 0][m0] = tf32r(lb0.x); Bs[buf][kk0 + 1][m0] = tf32r(lb0.y); \
        Bs[buf][kk0 + 2][m0] = tf32r(lb0.z); Bs[buf][kk0 + 3][m0] = tf32r(lb0.w); \
        Bs[buf][kk1 + 0][m1] = tf32r(lb1.x); Bs[buf][kk1 + 1][m1] = tf32r(lb1.y); \
        Bs[buf][kk1 + 2][m1] = tf32r(lb1.z); Bs[buf][kk1 + 3][m1] = tf32r(lb1.w); \
    }

    G_LOAD(0);
    S_STORE(0);
    __syncthreads();

    const int rr = lane >> 2;
    const int kc = lane & 3;
    const int NK = DD / 16;

    for (int kt = 0; kt < NK; kt++) {
        int cur = kt & 1;
        if (kt + 1 < NK) G_LOAD(kt + 1);
#pragma unroll
        for (int ks = 0; ks < 16; ks += 8) {
            unsigned af[4][4], bf[4][2];
#pragma unroll
            for (int mi = 0; mi < 4; mi++) {
                af[mi][0] = __float_as_uint(As[cur][ks + kc][wm + mi * 16 + rr]);
                af[mi][1] = __float_as_uint(As[cur][ks + kc][wm + mi * 16 + rr + 8]);
                af[mi][2] = __float_as_uint(As[cur][ks + kc + 4][wm + mi * 16 + rr]);
                af[mi][3] = __float_as_uint(As[cur][ks + kc + 4][wm + mi * 16 + rr + 8]);
            }
#pragma unroll
            for (int nj = 0; nj < 4; nj++) {
                bf[nj][0] = __float_as_uint(Bs[cur][ks + kc][wn + nj * 8 + rr]);
                bf[nj][1] = __float_as_uint(Bs[cur][ks + kc + 4][wn + nj * 8 + rr]);
            }
#pragma unroll
            for (int mi = 0; mi < 4; mi++)
#pragma unroll
                for (int nj = 0; nj < 4; nj++) MMA_TF32(acc[mi][nj], af[mi], bf[nj]);
        }
        if (kt + 1 < NK) {
            S_STORE(cur ^ 1);
            __syncthreads();
        }
    }

#pragma unroll
    for (int mi = 0; mi < 4; mi++) {
#pragma unroll
        for (int nj = 0; nj < 4; nj++) {
            int r0 = bm + wm + mi * 16 + rr;
            int c0 = bn + wn + nj * 8 + (kc << 1);
            float2 v0 = make_float2(acc[mi][nj][0], acc[mi][nj][1]);
            float2 v1 = make_float2(acc[mi][nj][2], acc[mi][nj][3]);
            *(float2*)(C + (size_t)r0 * VV + c0) = v0;
            *(float2*)(C + (size_t)(r0 + 8) * VV + c0) = v1;
        }
    }
}

// ---------------- launcher ----------------
extern "C" void kernel_launch(void* const* d_in, const int* in_sizes, int n_in,
                              void* d_out, int out_size) {
    const int* idx = (const int*)d_in[0];
    const int* pK = (const int*)d_in[1];
    const float* wte = (const float*)d_in[2];
    const float* wpe = (const float*)d_in[3];
    const float* bseq_w = (const float*)d_in[4];
    const float* logA_seq = (const float*)d_in[5];
    const float* logdt_seq = (const float*)d_in[6];
    const float* bdepth_w = (const float*)d_in[7];
    const float* logA_depth = (const float*)d_in[8];
    const float* logdt_depth = (const float*)d_in[9];
    const float* wpost_w = (const float*)d_in[10];
    const float* wlocal_w = (const float*)d_in[11];
    const float* lowA = (const float*)d_in[12];
    const float* lowB = (const float*)d_in[13];
    const float* lm_head_w = (const float*)d_in[14];
    float* out = (float*)d_out;

    float *x, *e, *h, *ud, *c, *r, *tmp, *xn, *seg;
    cudaGetSymbolAddress((void**)&x, g_x);
    cudaGetSymbolAddress((void**)&e, g_e);
    cudaGetSymbolAddress((void**)&h, g_h);
    cudaGetSymbolAddress((void**)&ud, g_ud);
    cudaGetSymbolAddress((void**)&c, g_c);
    cudaGetSymbolAddress((void**)&r, g_r);
    cudaGetSymbolAddress((void**)&tmp, g_tmp);
    cudaGetSymbolAddress((void**)&xn, g_xn);
    cudaGetSymbolAddress((void**)&seg, g_seg);

    embed_kernel<<<TT, 256>>>(idx, wte, wpe, x);

    for (int l = 0; l < LYR; l++) {
        const float* bseq_l = bseq_w + l * NBLK * 64 * 64;
        const float* lAs = logA_seq + l * HH;
        const float* lDs = logdt_seq + l * HH;
        const float* bdep_l = bdepth_w + l * NBLK * 64 * 64;
        const float* lAd = logA_depth + l * (HH - NMEM);
        const float* lDd = logdt_depth + l * (HH - NMEM);
        const float* wpost_l = wpost_w + l * NBLK * 64 * 192;
        const float* wlocal_l = wlocal_w + l * NBLK * 64 * 64;
        const float* lowA_l = lowA + l * DD * RANKK;
        const float* lowB_l = lowB + l * RANKK * HH;

        rmsnorm_kernel<<<TT, 256>>>(x, e);
        bd64_dual_kernel<<<dim3(TT / 64, NBLK), 256>>>(e, bseq_l, bdep_l, h, ud);
        scanA_kernel<<<dim3(32, 8), dim3(32, 8)>>>(h, lAs, lDs, seg);
        scanB_kernel<<<DD / 16, dim3(16, NSEG)>>>(seg, lAs, lDs);
        scanC_kernel<<<dim3(32, 8), dim3(32, 8)>>>(h, lAs, lDs, seg);
        combine_prep_kernel<<<TT, 256>>>(h, ud, e, lAd, lDd, pK, c);
        bd192_kernel<<<dim3(TT / 64, NBLK), 256>>>(c, wpost_l, r);
        lowrank1_kernel<<<TT / 16, 256>>>(r, lowB_l, tmp);
        update_kernel<<<dim3(TT / 64, NBLK), 256>>>(x, r, tmp, wlocal_l, lowA_l);
    }

    rmsnorm_kernel<<<TT, 256>>>(x, xn);
    lmhead_gemm<<<dim3(VV / 128, TT / 128), 256>>>(xn, lm_head_w, out);
}